// round 1
// baseline (speedup 1.0000x reference)
#include <cuda_runtime.h>
#include <math.h>

// ----------------------------------------------------------------------------
// Problem constants (fixed shapes)
// ----------------------------------------------------------------------------
#define T_STEPS 4096
#define INP_DIM 512
#define HID     1024
#define GATES   4096   // 4*HID

// Recurrent kernel config
#define NCTA      128           // CTAs; each owns 8 hidden columns
#define COLS      8             // columns per CTA
#define NTHREADS  256           // 8 warps; warp w owns column j0+w
// SMEM: sW1[40*1024] (4 gates + W_hr per col), sW2[8*1024] (W_cr), sh[1024], sc[1024]
#define SMEM_FLOATS (40*1024 + 8*1024 + 1024 + 1024)
#define SMEM_BYTES  (SMEM_FLOATS * 4)

// ----------------------------------------------------------------------------
// Device scratch (allocation-free: __device__ globals)
// ----------------------------------------------------------------------------
__device__ float g_xp[(size_t)T_STEPS * GATES];  // 64 MB: x @ W_xg
__device__ float g_h[HID];
__device__ float g_c[HID];
__device__ unsigned int g_count;
__device__ unsigned int g_gen;

// ----------------------------------------------------------------------------
// Grid-wide barrier (all NCTA CTAs resident: 1 CTA/SM, grid < SM count)
// ----------------------------------------------------------------------------
__device__ __forceinline__ void grid_bar() {
    __syncthreads();
    if (threadIdx.x == 0) {
        __threadfence();  // make prior global writes visible before arriving
        volatile unsigned int* genp = &g_gen;
        unsigned int old_gen = *genp;
        __threadfence();
        unsigned int prev = atomicAdd(&g_count, 1u);
        if (prev == NCTA - 1u) {
            atomicExch(&g_count, 0u);
            __threadfence();
            *genp = old_gen + 1u;  // release
        } else {
            while (*genp == old_gen) { }
        }
        __threadfence();  // acquire: order subsequent reads after release observed
    }
    __syncthreads();
}

// ----------------------------------------------------------------------------
// Kernel 1: x_proj = x @ W_xg   (fp32 SGEMM, 128x128 tile, BK=16, 8x8/thread)
// ----------------------------------------------------------------------------
#define BSP 132   // padded SMEM row (multiple of 4 for float4 alignment)

__global__ void __launch_bounds__(256)
sgemm_xproj(const float* __restrict__ A,   // x      [4096, 512]
            const float* __restrict__ B)   // W_xg   [512, 4096]
{
    __shared__ float As[16 * BSP];
    __shared__ float Bs[16 * BSP];

    const int tid = threadIdx.x;
    const int bm  = blockIdx.y;       // row tile
    const int bn  = blockIdx.x;       // col tile
    const int ty  = tid >> 4;         // 0..15
    const int tx  = tid & 15;         // 0..15

    float acc[8][8];
#pragma unroll
    for (int i = 0; i < 8; i++)
#pragma unroll
        for (int j = 0; j < 8; j++) acc[i][j] = 0.f;

    for (int kt = 0; kt < INP_DIM / 16; kt++) {
        // Load A tile 128x16 -> As[k][m] (transposed)
#pragma unroll
        for (int s = 0; s < 2; s++) {
            int f   = tid + s * 256;
            int row = f >> 2;          // 0..127
            int kq  = f & 3;           // 0..3 (float4 along k)
            float4 av = *(const float4*)(A + (size_t)(bm * 128 + row) * INP_DIM
                                           + kt * 16 + kq * 4);
            As[(kq * 4 + 0) * BSP + row] = av.x;
            As[(kq * 4 + 1) * BSP + row] = av.y;
            As[(kq * 4 + 2) * BSP + row] = av.z;
            As[(kq * 4 + 3) * BSP + row] = av.w;
        }
        // Load B tile 16x128 -> Bs[k][n]
#pragma unroll
        for (int s = 0; s < 2; s++) {
            int f  = tid + s * 256;
            int kk = f >> 5;           // 0..15
            int cq = f & 31;           // 0..31 (float4 along n)
            float4 bv = *(const float4*)(B + (size_t)(kt * 16 + kk) * GATES
                                           + bn * 128 + cq * 4);
            *(float4*)(&Bs[kk * BSP + cq * 4]) = bv;
        }
        __syncthreads();

#pragma unroll
        for (int kk = 0; kk < 16; kk++) {
            float4 a0 = *(const float4*)(&As[kk * BSP + ty * 8]);
            float4 a1 = *(const float4*)(&As[kk * BSP + ty * 8 + 4]);
            float4 b0 = *(const float4*)(&Bs[kk * BSP + tx * 8]);
            float4 b1 = *(const float4*)(&Bs[kk * BSP + tx * 8 + 4]);
            float ar[8] = {a0.x, a0.y, a0.z, a0.w, a1.x, a1.y, a1.z, a1.w};
            float br[8] = {b0.x, b0.y, b0.z, b0.w, b1.x, b1.y, b1.z, b1.w};
#pragma unroll
            for (int i = 0; i < 8; i++)
#pragma unroll
                for (int j = 0; j < 8; j++) acc[i][j] += ar[i] * br[j];
        }
        __syncthreads();
    }

    // Epilogue -> g_xp
#pragma unroll
    for (int i = 0; i < 8; i++) {
        size_t base = (size_t)(bm * 128 + ty * 8 + i) * GATES + bn * 128 + tx * 8;
        *(float4*)(&g_xp[base])     = make_float4(acc[i][0], acc[i][1], acc[i][2], acc[i][3]);
        *(float4*)(&g_xp[base + 4]) = make_float4(acc[i][4], acc[i][5], acc[i][6], acc[i][7]);
    }
}

// ----------------------------------------------------------------------------
// Kernel 2: persistent recurrent LSTM. 128 CTAs x 256 threads.
// Warp w of CTA b owns hidden column j = 8*b + w:
//   phase 1: dots o,f,i,g (W_hg cols) + r1 (W_hr col) against h_{t-1};
//            pointwise -> c_t[j], o[j]; publish c_t
//   barrier
//   phase 2: r2 = c_t . W_cr[:,j]; h_t[j] = o * tanh(r1 + r2 + b_r); publish h_t
//   barrier
// ----------------------------------------------------------------------------
__global__ void __launch_bounds__(NTHREADS, 1)
lstm_recur(const float* __restrict__ W_hg,   // [1024, 4096]
           const float* __restrict__ W_hr,   // [1024, 1024]
           const float* __restrict__ W_cr,   // [1024, 1024]
           const float* __restrict__ b_g,    // [4096]
           const float* __restrict__ b_r,    // [1024]
           float* __restrict__ out)          // [4096, 1024]
{
    extern __shared__ float smem[];
    float* sW1 = smem;                 // 40*1024 : dot d = i*8+w, i in 0..4
    float* sW2 = smem + 40 * 1024;     //  8*1024 : W_cr columns
    float* sh  = smem + 48 * 1024;     //  1024
    float* sc  = smem + 49 * 1024;     //  1024

    const int tid  = threadIdx.x;
    const int w    = tid >> 5;
    const int lane = tid & 31;
    const int j0   = blockIdx.x * COLS;
    const int j    = j0 + w;

    // ---- One-time weight staging into SMEM ----
#pragma unroll
    for (int i = 0; i < 5; i++) {
        for (int idx = tid; idx < COLS * 1024; idx += NTHREADS) {
            int cl = idx & 7;
            int k  = idx >> 3;
            float v = (i < 4) ? W_hg[(size_t)k * GATES + i * HID + j0 + cl]
                              : W_hr[(size_t)k * HID + j0 + cl];
            sW1[(size_t)(i * 8 + cl) * 1024 + k] = v;
        }
    }
    for (int idx = tid; idx < COLS * 1024; idx += NTHREADS) {
        int cl = idx & 7;
        int k  = idx >> 3;
        sW2[(size_t)cl * 1024 + k] = W_cr[(size_t)k * HID + j0 + cl];
    }
    __syncthreads();

    // Lane-0 constants
    float bg0 = 0.f, bg1 = 0.f, bg2 = 0.f, bg3 = 0.f, brj = 0.f;
    if (lane == 0) {
        bg0 = b_g[j];
        bg1 = b_g[HID + j];
        bg2 = b_g[2 * HID + j];
        bg3 = b_g[3 * HID + j];
        brj = b_r[j];
    }

    float c_state = 0.f;
    float4 hreg[8];
#pragma unroll
    for (int q = 0; q < 8; q++) hreg[q] = make_float4(0.f, 0.f, 0.f, 0.f);

    const float4* w1v = (const float4*)sW1;
    const float4* w2v = (const float4*)sW2;

    for (int t = 0; t < T_STEPS; t++) {
        // Prefetch x_proj entries (lane 0) — consumed after the dot loop
        float xpo = 0.f, xpf = 0.f, xpi = 0.f, xpg = 0.f;
        if (lane == 0) {
            const float* xpt = g_xp + (size_t)t * GATES;
            xpo = xpt[j];
            xpf = xpt[HID + j];
            xpi = xpt[2 * HID + j];
            xpg = xpt[3 * HID + j];
        }

        // ---- Phase 1: 5 dots against h_{t-1} (in hreg) ----
        float s[5];
#pragma unroll
        for (int i = 0; i < 5; i++) {
            const float4* wp = w1v + (size_t)(i * 8 + w) * 256;
            float acc = 0.f;
#pragma unroll
            for (int q = 0; q < 8; q++) {
                float4 wv = wp[lane + 32 * q];
                float4 hv = hreg[q];
                acc += wv.x * hv.x + wv.y * hv.y + wv.z * hv.z + wv.w * hv.w;
            }
#pragma unroll
            for (int off = 16; off; off >>= 1)
                acc += __shfl_xor_sync(0xffffffffu, acc, off);
            s[i] = acc;
        }

        float o_val = 0.f, r1 = 0.f;
        if (lane == 0) {
            float go = s[0] + xpo + bg0;
            float gf = s[1] + xpf + bg1;
            float gi = s[2] + xpi + bg2;
            float gg = s[3] + xpg + bg3;
            float f_t = 1.f / (1.f + expf(-gf));
            float i_t = 1.f / (1.f + expf(-gi));
            o_val = 1.f / (1.f + expf(-go));
            c_state = f_t * c_state + i_t * tanhf(gg);
            g_c[j] = c_state;
            r1 = s[4];
        }

        grid_bar();  // c_t globally visible

        // Stage c into SMEM, then phase-2 dot
        ((float4*)sc)[tid] = ((const float4*)g_c)[tid];
        __syncthreads();

        const float4* wp2 = w2v + (size_t)w * 256;
        const float4* scv = (const float4*)sc;
        float acc2 = 0.f;
#pragma unroll
        for (int q = 0; q < 8; q++) {
            float4 wv = wp2[lane + 32 * q];
            float4 cv = scv[lane + 32 * q];
            acc2 += wv.x * cv.x + wv.y * cv.y + wv.z * cv.z + wv.w * cv.w;
        }
#pragma unroll
        for (int off = 16; off; off >>= 1)
            acc2 += __shfl_xor_sync(0xffffffffu, acc2, off);

        if (lane == 0) {
            float hn = o_val * tanhf(r1 + acc2 + brj);
            out[(size_t)t * HID + j] = hn;
            g_h[j] = hn;
        }

        grid_bar();  // h_t globally visible

        // Stage h into SMEM and reload hreg for next step
        ((float4*)sh)[tid] = ((const float4*)g_h)[tid];
        __syncthreads();
#pragma unroll
        for (int q = 0; q < 8; q++)
            hreg[q] = ((const float4*)sh)[lane + 32 * q];
    }
}

// ----------------------------------------------------------------------------
// Launch
// ----------------------------------------------------------------------------
extern "C" void kernel_launch(void* const* d_in, const int* in_sizes, int n_in,
                              void* d_out, int out_size) {
    const float* x    = (const float*)d_in[0];   // [4096, 512]
    const float* W_xg = (const float*)d_in[1];   // [512, 4096]
    const float* W_hg = (const float*)d_in[2];   // [1024, 4096]
    const float* b_g  = (const float*)d_in[3];   // [1, 4096]
    const float* W_cr = (const float*)d_in[4];   // [1024, 1024]
    const float* W_hr = (const float*)d_in[5];   // [1024, 1024]
    const float* b_r  = (const float*)d_in[6];   // [1, 1024]
    float* out = (float*)d_out;                  // [4096, 1, 1024]

    (void)in_sizes; (void)n_in; (void)out_size;

    // Kernel 1: x_proj
    dim3 ggrid(GATES / 128, T_STEPS / 128);
    sgemm_xproj<<<ggrid, 256>>>(x, W_xg);

    // Kernel 2: persistent recurrence
    cudaFuncSetAttribute(lstm_recur, cudaFuncAttributeMaxDynamicSharedMemorySize,
                         SMEM_BYTES);
    lstm_recur<<<NCTA, NTHREADS, SMEM_BYTES>>>(W_hg, W_hr, W_cr, b_g, b_r, out);
}

// round 2
// speedup vs baseline: 1.8414x; 1.8414x over previous
#include <cuda_runtime.h>
#include <math.h>

// ----------------------------------------------------------------------------
// Problem constants (fixed shapes)
// ----------------------------------------------------------------------------
#define T_STEPS 4096
#define INP_DIM 512
#define HID     1024
#define GATES   4096   // 4*HID

// Recurrent kernel config
#define NCTA      128           // CTAs; each owns 8 hidden columns
#define COLS      8             // columns per CTA
#define NTHREADS  256           // 8 warps; warp w owns column j0+w

// SMEM layout (floats):
//   sW1     [2*8*1024]  : 2 SMEM-resident dots per column (g-gate, W_hr)
//   scratch [8*1024]    : staging buffer for register weights
//   sc      [1024]      : broadcast c_t
//   sh      [1024]      : broadcast h_t
#define SW1_F     (2 * 8 * 1024)
#define SCR_F     (8 * 1024)
#define SMEM_FLOATS (SW1_F + SCR_F + 1024 + 1024)
#define SMEM_BYTES  (SMEM_FLOATS * 4)

// ----------------------------------------------------------------------------
// Device scratch (allocation-free: __device__ globals)
// ----------------------------------------------------------------------------
__device__ float g_xp[(size_t)T_STEPS * GATES];           // 64 MB: x @ W_xg
__device__ unsigned long long g_cpack[HID];               // (tag<<32)|c bits
__device__ unsigned long long g_hpack[HID];               // (tag<<32)|h bits

// ----------------------------------------------------------------------------
// Kernel 1: x_proj = x @ W_xg   (fp32 SGEMM, 128x128 tile, BK=16, 8x8/thread)
// ----------------------------------------------------------------------------
#define BSP 132   // padded SMEM row

__global__ void __launch_bounds__(256)
sgemm_xproj(const float* __restrict__ A,   // x      [4096, 512]
            const float* __restrict__ B)   // W_xg   [512, 4096]
{
    __shared__ float As[16 * BSP];
    __shared__ float Bs[16 * BSP];

    const int tid = threadIdx.x;
    const int bm  = blockIdx.y;
    const int bn  = blockIdx.x;
    const int ty  = tid >> 4;
    const int tx  = tid & 15;

    float acc[8][8];
#pragma unroll
    for (int i = 0; i < 8; i++)
#pragma unroll
        for (int j = 0; j < 8; j++) acc[i][j] = 0.f;

    for (int kt = 0; kt < INP_DIM / 16; kt++) {
#pragma unroll
        for (int s = 0; s < 2; s++) {
            int f   = tid + s * 256;
            int row = f >> 2;
            int kq  = f & 3;
            float4 av = *(const float4*)(A + (size_t)(bm * 128 + row) * INP_DIM
                                           + kt * 16 + kq * 4);
            As[(kq * 4 + 0) * BSP + row] = av.x;
            As[(kq * 4 + 1) * BSP + row] = av.y;
            As[(kq * 4 + 2) * BSP + row] = av.z;
            As[(kq * 4 + 3) * BSP + row] = av.w;
        }
#pragma unroll
        for (int s = 0; s < 2; s++) {
            int f  = tid + s * 256;
            int kk = f >> 5;
            int cq = f & 31;
            float4 bv = *(const float4*)(B + (size_t)(kt * 16 + kk) * GATES
                                           + bn * 128 + cq * 4);
            *(float4*)(&Bs[kk * BSP + cq * 4]) = bv;
        }
        __syncthreads();

#pragma unroll
        for (int kk = 0; kk < 16; kk++) {
            float4 a0 = *(const float4*)(&As[kk * BSP + ty * 8]);
            float4 a1 = *(const float4*)(&As[kk * BSP + ty * 8 + 4]);
            float4 b0 = *(const float4*)(&Bs[kk * BSP + tx * 8]);
            float4 b1 = *(const float4*)(&Bs[kk * BSP + tx * 8 + 4]);
            float ar[8] = {a0.x, a0.y, a0.z, a0.w, a1.x, a1.y, a1.z, a1.w};
            float br[8] = {b0.x, b0.y, b0.z, b0.w, b1.x, b1.y, b1.z, b1.w};
#pragma unroll
            for (int i = 0; i < 8; i++)
#pragma unroll
                for (int j = 0; j < 8; j++) acc[i][j] += ar[i] * br[j];
        }
        __syncthreads();
    }

#pragma unroll
    for (int i = 0; i < 8; i++) {
        size_t base = (size_t)(bm * 128 + ty * 8 + i) * GATES + bn * 128 + tx * 8;
        *(float4*)(&g_xp[base])     = make_float4(acc[i][0], acc[i][1], acc[i][2], acc[i][3]);
        *(float4*)(&g_xp[base + 4]) = make_float4(acc[i][4], acc[i][5], acc[i][6], acc[i][7]);
    }
}

// ----------------------------------------------------------------------------
// Fast pointwise (fp32, ~1e-6 rel err)
// ----------------------------------------------------------------------------
__device__ __forceinline__ float fsigmoid(float x) {
    return 1.0f / (1.0f + __expf(-x));
}
__device__ __forceinline__ float ftanh(float x) {
    // tanh(x) = 1 - 2/(exp(2x)+1)
    return 1.0f - 2.0f / (__expf(2.0f * x) + 1.0f);
}

// ----------------------------------------------------------------------------
// Tag-stamped broadcast: producer packs (tag, value) into one 8B word;
// consumers poll 4 columns each and drop values into SMEM. This is both the
// barrier and the data exchange — no atomics, no fences, no extra staging.
// 8B aligned volatile ld/st are single-copy atomic, so tag and value are
// always consistent.
// ----------------------------------------------------------------------------
__device__ __forceinline__ void publish(unsigned long long* arr, int j,
                                        unsigned tag, float v) {
    unsigned long long p = ((unsigned long long)tag << 32) | (unsigned long long)__float_as_uint(v);
    *((volatile unsigned long long*)(arr + j)) = p;
}

__device__ __forceinline__ void poll_gather(const unsigned long long* arr,
                                            unsigned tag, float* dst, int tid) {
    const volatile unsigned long long* src = (const volatile unsigned long long*)arr;
    const int c0 = tid, c1 = tid + 256, c2 = tid + 512, c3 = tid + 768;
    unsigned got = 0;
    while (got != 0xFu) {
        if (!(got & 1u)) {
            unsigned long long v = src[c0];
            if ((unsigned)(v >> 32) == tag) { dst[c0] = __uint_as_float((unsigned)v); got |= 1u; }
        }
        if (!(got & 2u)) {
            unsigned long long v = src[c1];
            if ((unsigned)(v >> 32) == tag) { dst[c1] = __uint_as_float((unsigned)v); got |= 2u; }
        }
        if (!(got & 4u)) {
            unsigned long long v = src[c2];
            if ((unsigned)(v >> 32) == tag) { dst[c2] = __uint_as_float((unsigned)v); got |= 4u; }
        }
        if (!(got & 8u)) {
            unsigned long long v = src[c3];
            if ((unsigned)(v >> 32) == tag) { dst[c3] = __uint_as_float((unsigned)v); got |= 8u; }
        }
    }
}

// ----------------------------------------------------------------------------
// Kernel 2: persistent recurrence. 128 CTAs x 256 threads; warp w owns
// column j = 8*blockIdx.x + w.
// Register-resident: gates o,f,i (W_hg cols 0..2H) and W_cr column.
// SMEM-resident:     gate g (W_hg col 3H..4H) and W_hr column.
// h_{t-1} lives in registers (hreg, float4 x8 per lane).
// ----------------------------------------------------------------------------
__global__ void __launch_bounds__(NTHREADS, 1)
lstm_recur(const float* __restrict__ W_hg,   // [1024, 4096]
           const float* __restrict__ W_hr,   // [1024, 1024]
           const float* __restrict__ W_cr,   // [1024, 1024]
           const float* __restrict__ b_g,    // [4096]
           const float* __restrict__ b_r,    // [1024]
           float* __restrict__ out)          // [4096, 1024]
{
    extern __shared__ float smem[];
    float* sW1     = smem;                    // 2*8*1024 (slot0: g-gate, slot1: W_hr)
    float* scratch = smem + SW1_F;            // 8*1024
    float* sc      = smem + SW1_F + SCR_F;    // 1024
    float* sh      = sc + 1024;               // 1024

    const int tid  = threadIdx.x;
    const int w    = tid >> 5;
    const int lane = tid & 31;
    const int j0   = blockIdx.x * COLS;
    const int j    = j0 + w;

    // ---- Stage SMEM-resident weights (coalesced) ----
    // slot 0: W_hg gate 3 (g); slot 1: W_hr
    for (int idx = tid; idx < COLS * 1024; idx += NTHREADS) {
        int cl = idx & 7;
        int k  = idx >> 3;
        sW1[(size_t)(0 * 8 + cl) * 1024 + k] = W_hg[(size_t)k * GATES + 3 * HID + j0 + cl];
        sW1[(size_t)(1 * 8 + cl) * 1024 + k] = W_hr[(size_t)k * HID + j0 + cl];
    }

    // ---- Stage register weights via scratch (coalesced global -> SMEM -> regs)
    // Layout contract: hreg[q].{x..w} = h[128q + 4*lane + d]
    //   => wreg[q] must hold W[(128q+4lane+d)*stride + col]
    //   scratch[cl*1024 + k] read back as float4 at index w*256 + 32q + lane.
    float4 wo[8], wf[8], wi[8], wcr[8];
    const float4* scrv = (const float4*)scratch;
#pragma unroll
    for (int g = 0; g < 4; g++) {
        __syncthreads();
        for (int idx = tid; idx < COLS * 1024; idx += NTHREADS) {
            int cl = idx & 7;
            int k  = idx >> 3;
            float v;
            if (g < 3) v = W_hg[(size_t)k * GATES + g * HID + j0 + cl];
            else       v = W_cr[(size_t)k * HID + j0 + cl];
            scratch[(size_t)cl * 1024 + k] = v;
        }
        __syncthreads();
#pragma unroll
        for (int q = 0; q < 8; q++) {
            float4 v = scrv[w * 256 + 32 * q + lane];
            if (g == 0) wo[q] = v;
            else if (g == 1) wf[q] = v;
            else if (g == 2) wi[q] = v;
            else wcr[q] = v;
        }
    }
    __syncthreads();

    // Lane-0 constants
    float bg0 = 0.f, bg1 = 0.f, bg2 = 0.f, bg3 = 0.f, brj = 0.f;
    if (lane == 0) {
        bg0 = b_g[j];
        bg1 = b_g[HID + j];
        bg2 = b_g[2 * HID + j];
        bg3 = b_g[3 * HID + j];
        brj = b_r[j];
    }

    float c_state = 0.f;
    float4 hreg[8];
#pragma unroll
    for (int q = 0; q < 8; q++) hreg[q] = make_float4(0.f, 0.f, 0.f, 0.f);

    const float4* w1v = (const float4*)sW1;
    const float4* scv = (const float4*)sc;
    const float4* shv = (const float4*)sh;

    for (int t = 0; t < T_STEPS; t++) {
        const unsigned tag = (unsigned)(t + 1);

        // Prefetch x_proj entries (lane 0)
        float xpo = 0.f, xpf = 0.f, xpi = 0.f, xpg = 0.f;
        if (lane == 0) {
            const float* xpt = g_xp + (size_t)t * GATES;
            xpo = xpt[j];
            xpf = xpt[HID + j];
            xpi = xpt[2 * HID + j];
            xpg = xpt[3 * HID + j];
        }

        // ---- Phase 1: 5 dots against h_{t-1} ----
        float ao = 0.f, af = 0.f, ai = 0.f, ag = 0.f, ar = 0.f;
        const float4* wpg = w1v + (size_t)(0 * 8 + w) * 256;
        const float4* wpr = w1v + (size_t)(1 * 8 + w) * 256;
#pragma unroll
        for (int q = 0; q < 8; q++) {
            float4 hv = hreg[q];
            float4 vo = wo[q], vf = wf[q], vi = wi[q];
            ao += vo.x * hv.x + vo.y * hv.y + vo.z * hv.z + vo.w * hv.w;
            af += vf.x * hv.x + vf.y * hv.y + vf.z * hv.z + vf.w * hv.w;
            ai += vi.x * hv.x + vi.y * hv.y + vi.z * hv.z + vi.w * hv.w;
            float4 vg = wpg[lane + 32 * q];
            ag += vg.x * hv.x + vg.y * hv.y + vg.z * hv.z + vg.w * hv.w;
            float4 vr = wpr[lane + 32 * q];
            ar += vr.x * hv.x + vr.y * hv.y + vr.z * hv.z + vr.w * hv.w;
        }
#pragma unroll
        for (int off = 16; off; off >>= 1) {
            ao += __shfl_xor_sync(0xffffffffu, ao, off);
            af += __shfl_xor_sync(0xffffffffu, af, off);
            ai += __shfl_xor_sync(0xffffffffu, ai, off);
            ag += __shfl_xor_sync(0xffffffffu, ag, off);
            ar += __shfl_xor_sync(0xffffffffu, ar, off);
        }

        float o_val = 0.f, r1 = 0.f;
        if (lane == 0) {
            float f_t = fsigmoid(af + xpf + bg1);
            float i_t = fsigmoid(ai + xpi + bg2);
            o_val = fsigmoid(ao + xpo + bg0);
            c_state = f_t * c_state + i_t * ftanh(ag + xpg + bg3);
            r1 = ar;
            publish(g_cpack, j, tag, c_state);   // barrier-1 + data, fused
        }

        // ---- Gather c_t (acts as grid barrier) ----
        poll_gather(g_cpack, tag, sc, tid);
        __syncthreads();

        // ---- Phase 2: r2 = c_t . W_cr[:,j] (register weights) ----
        float a2 = 0.f;
#pragma unroll
        for (int q = 0; q < 8; q++) {
            float4 cv = scv[lane + 32 * q];
            float4 wv = wcr[q];
            a2 += wv.x * cv.x + wv.y * cv.y + wv.z * cv.z + wv.w * cv.w;
        }
#pragma unroll
        for (int off = 16; off; off >>= 1)
            a2 += __shfl_xor_sync(0xffffffffu, a2, off);

        if (lane == 0) {
            float hn = o_val * ftanh(r1 + a2 + brj);
            out[(size_t)t * HID + j] = hn;
            publish(g_hpack, j, tag, hn);        // barrier-2 + data, fused
        }

        // ---- Gather h_t ----
        poll_gather(g_hpack, tag, sh, tid);
        __syncthreads();
#pragma unroll
        for (int q = 0; q < 8; q++)
            hreg[q] = shv[lane + 32 * q];
    }
}

// ----------------------------------------------------------------------------
// Launch
// ----------------------------------------------------------------------------
extern "C" void kernel_launch(void* const* d_in, const int* in_sizes, int n_in,
                              void* d_out, int out_size) {
    const float* x    = (const float*)d_in[0];   // [4096, 512]
    const float* W_xg = (const float*)d_in[1];   // [512, 4096]
    const float* W_hg = (const float*)d_in[2];   // [1024, 4096]
    const float* b_g  = (const float*)d_in[3];   // [1, 4096]
    const float* W_cr = (const float*)d_in[4];   // [1024, 1024]
    const float* W_hr = (const float*)d_in[5];   // [1024, 1024]
    const float* b_r  = (const float*)d_in[6];   // [1, 1024]
    float* out = (float*)d_out;                  // [4096, 1, 1024]

    (void)in_sizes; (void)n_in; (void)out_size;

    dim3 ggrid(GATES / 128, T_STEPS / 128);
    sgemm_xproj<<<ggrid, 256>>>(x, W_xg);

    cudaFuncSetAttribute(lstm_recur, cudaFuncAttributeMaxDynamicSharedMemorySize,
                         SMEM_BYTES);
    lstm_recur<<<NCTA, NTHREADS, SMEM_BYTES>>>(W_hg, W_hr, W_cr, b_g, b_r, out);
}

// round 3
// speedup vs baseline: 2.3597x; 1.2815x over previous
#include <cuda_runtime.h>
#include <math.h>

// ----------------------------------------------------------------------------
// Problem constants (fixed shapes)
// ----------------------------------------------------------------------------
#define T_STEPS 4096
#define INP_DIM 512
#define HID     1024
#define GATES   4096   // 4*HID

// Recurrent kernel config
#define NCTA      128           // CTAs; each owns 8 hidden columns
#define COLS      8             // columns per CTA
#define NTHREADS  256           // 8 warps; warp w owns column j0+w

// SMEM layout (floats):
//   sW1     [2*8*1024]  : 2 SMEM-resident dots per column (g-gate, W_hr)
//   scratch [8*1024]    : staging buffer for register weights
//   sc      [1024]      : broadcast c_t
//   sh      [1024]      : broadcast h_t
#define SW1_F     (2 * 8 * 1024)
#define SCR_F     (8 * 1024)
#define SMEM_FLOATS (SW1_F + SCR_F + 1024 + 1024)
#define SMEM_BYTES  (SMEM_FLOATS * 4)

// ----------------------------------------------------------------------------
// Device scratch (allocation-free: __device__ globals)
// ----------------------------------------------------------------------------
__device__ float g_xp[(size_t)T_STEPS * GATES];           // 64 MB: x @ W_xg
__device__ unsigned long long g_cpack[HID];               // (tag<<32)|c bits
__device__ unsigned long long g_hpack[HID];               // (tag<<32)|h bits

// ----------------------------------------------------------------------------
// Kernel 1: x_proj = x @ W_xg   (fp32 SGEMM, 128x128 tile, BK=16, 8x8/thread)
// ----------------------------------------------------------------------------
#define BSP 132   // padded SMEM row

__global__ void __launch_bounds__(256)
sgemm_xproj(const float* __restrict__ A,   // x      [4096, 512]
            const float* __restrict__ B)   // W_xg   [512, 4096]
{
    __shared__ float As[16 * BSP];
    __shared__ float Bs[16 * BSP];

    const int tid = threadIdx.x;
    const int bm  = blockIdx.y;
    const int bn  = blockIdx.x;
    const int ty  = tid >> 4;
    const int tx  = tid & 15;

    float acc[8][8];
#pragma unroll
    for (int i = 0; i < 8; i++)
#pragma unroll
        for (int j = 0; j < 8; j++) acc[i][j] = 0.f;

    for (int kt = 0; kt < INP_DIM / 16; kt++) {
#pragma unroll
        for (int s = 0; s < 2; s++) {
            int f   = tid + s * 256;
            int row = f >> 2;
            int kq  = f & 3;
            float4 av = *(const float4*)(A + (size_t)(bm * 128 + row) * INP_DIM
                                           + kt * 16 + kq * 4);
            As[(kq * 4 + 0) * BSP + row] = av.x;
            As[(kq * 4 + 1) * BSP + row] = av.y;
            As[(kq * 4 + 2) * BSP + row] = av.z;
            As[(kq * 4 + 3) * BSP + row] = av.w;
        }
#pragma unroll
        for (int s = 0; s < 2; s++) {
            int f  = tid + s * 256;
            int kk = f >> 5;
            int cq = f & 31;
            float4 bv = *(const float4*)(B + (size_t)(kt * 16 + kk) * GATES
                                           + bn * 128 + cq * 4);
            *(float4*)(&Bs[kk * BSP + cq * 4]) = bv;
        }
        __syncthreads();

#pragma unroll
        for (int kk = 0; kk < 16; kk++) {
            float4 a0 = *(const float4*)(&As[kk * BSP + ty * 8]);
            float4 a1 = *(const float4*)(&As[kk * BSP + ty * 8 + 4]);
            float4 b0 = *(const float4*)(&Bs[kk * BSP + tx * 8]);
            float4 b1 = *(const float4*)(&Bs[kk * BSP + tx * 8 + 4]);
            float ar[8] = {a0.x, a0.y, a0.z, a0.w, a1.x, a1.y, a1.z, a1.w};
            float br[8] = {b0.x, b0.y, b0.z, b0.w, b1.x, b1.y, b1.z, b1.w};
#pragma unroll
            for (int i = 0; i < 8; i++)
#pragma unroll
                for (int j = 0; j < 8; j++) acc[i][j] += ar[i] * br[j];
        }
        __syncthreads();
    }

#pragma unroll
    for (int i = 0; i < 8; i++) {
        size_t base = (size_t)(bm * 128 + ty * 8 + i) * GATES + bn * 128 + tx * 8;
        *(float4*)(&g_xp[base])     = make_float4(acc[i][0], acc[i][1], acc[i][2], acc[i][3]);
        *(float4*)(&g_xp[base + 4]) = make_float4(acc[i][4], acc[i][5], acc[i][6], acc[i][7]);
    }
}

// ----------------------------------------------------------------------------
// Fast pointwise (fp32, ~1e-6 rel err)
// ----------------------------------------------------------------------------
__device__ __forceinline__ float fsigmoid(float x) {
    return 1.0f / (1.0f + __expf(-x));
}
__device__ __forceinline__ float ftanh(float x) {
    return 1.0f - 2.0f / (__expf(2.0f * x) + 1.0f);
}

// ----------------------------------------------------------------------------
// Tag-stamped broadcast. Producer: one volatile 8B store of (tag<<32)|bits.
// Consumer: thread tid polls 4 CONTIGUOUS words [4*tid, 4*tid+4) — one 32B
// sector — using v2.u64 volatile loads. Second pair is polled only after the
// first pair hits, throttling spin traffic. 8B volatile accesses are
// single-copy atomic, so tag+value are always consistent.
// ----------------------------------------------------------------------------
__device__ __forceinline__ void publish(unsigned long long* arr, int j,
                                        unsigned tag, float v) {
    unsigned long long p = ((unsigned long long)tag << 32) |
                           (unsigned long long)__float_as_uint(v);
    *((volatile unsigned long long*)(arr + j)) = p;
}

__device__ __forceinline__ void poll_gather4(const unsigned long long* arr,
                                             unsigned tag, float* dst, int tid) {
    const unsigned long long* p = arr + 4 * tid;
    unsigned long long a0, a1, b0, b1;
    for (;;) {
        asm volatile("ld.volatile.global.v2.u64 {%0,%1},[%2];"
                     : "=l"(a0), "=l"(a1) : "l"(p) : "memory");
        if ((unsigned)(a0 >> 32) == tag && (unsigned)(a1 >> 32) == tag) break;
    }
    for (;;) {
        asm volatile("ld.volatile.global.v2.u64 {%0,%1},[%2];"
                     : "=l"(b0), "=l"(b1) : "l"(p + 2) : "memory");
        if ((unsigned)(b0 >> 32) == tag && (unsigned)(b1 >> 32) == tag) break;
    }
    *(float4*)(dst + 4 * tid) = make_float4(__uint_as_float((unsigned)a0),
                                            __uint_as_float((unsigned)a1),
                                            __uint_as_float((unsigned)b0),
                                            __uint_as_float((unsigned)b1));
}

// ----------------------------------------------------------------------------
// Kernel 2: persistent recurrence. 128 CTAs x 256 threads; warp w owns
// column j = 8*blockIdx.x + w.
// Register-resident: gates o,f,i (W_hg cols) and W_cr column.
// SMEM-resident:     gate g and W_hr column.
// Critical-path split: publish c right after f/i/g; o and W_hr dots are
// computed while the c-exchange is in flight.
// ----------------------------------------------------------------------------
__global__ void __launch_bounds__(NTHREADS, 1)
lstm_recur(const float* __restrict__ W_hg,   // [1024, 4096]
           const float* __restrict__ W_hr,   // [1024, 1024]
           const float* __restrict__ W_cr,   // [1024, 1024]
           const float* __restrict__ b_g,    // [4096]
           const float* __restrict__ b_r,    // [1024]
           float* __restrict__ out)          // [4096, 1024]
{
    extern __shared__ float smem[];
    float* sW1     = smem;                    // 2*8*1024 (slot0: g-gate, slot1: W_hr)
    float* scratch = smem + SW1_F;            // 8*1024
    float* sc      = smem + SW1_F + SCR_F;    // 1024
    float* sh      = sc + 1024;               // 1024

    const int tid  = threadIdx.x;
    const int w    = tid >> 5;
    const int lane = tid & 31;
    const int j0   = blockIdx.x * COLS;
    const int j    = j0 + w;

    // ---- Stage SMEM-resident weights (coalesced) ----
    for (int idx = tid; idx < COLS * 1024; idx += NTHREADS) {
        int cl = idx & 7;
        int k  = idx >> 3;
        sW1[(size_t)(0 * 8 + cl) * 1024 + k] = W_hg[(size_t)k * GATES + 3 * HID + j0 + cl];
        sW1[(size_t)(1 * 8 + cl) * 1024 + k] = W_hr[(size_t)k * HID + j0 + cl];
    }

    // ---- Stage register weights via scratch ----
    // Contract: hreg[q].{x..w} = h[128q + 4*lane + d]
    float4 wo[8], wf[8], wi[8], wcr[8];
    const float4* scrv = (const float4*)scratch;
#pragma unroll
    for (int g = 0; g < 4; g++) {
        __syncthreads();
        for (int idx = tid; idx < COLS * 1024; idx += NTHREADS) {
            int cl = idx & 7;
            int k  = idx >> 3;
            float v;
            if (g < 3) v = W_hg[(size_t)k * GATES + g * HID + j0 + cl];
            else       v = W_cr[(size_t)k * HID + j0 + cl];
            scratch[(size_t)cl * 1024 + k] = v;
        }
        __syncthreads();
#pragma unroll
        for (int q = 0; q < 8; q++) {
            float4 v = scrv[w * 256 + 32 * q + lane];
            if (g == 0) wo[q] = v;
            else if (g == 1) wf[q] = v;
            else if (g == 2) wi[q] = v;
            else wcr[q] = v;
        }
    }
    __syncthreads();

    // Lane-0 constants
    float bg0 = 0.f, bg1 = 0.f, bg2 = 0.f, bg3 = 0.f, brj = 0.f;
    if (lane == 0) {
        bg0 = b_g[j];
        bg1 = b_g[HID + j];
        bg2 = b_g[2 * HID + j];
        bg3 = b_g[3 * HID + j];
        brj = b_r[j];
    }

    float c_state = 0.f;
    float4 hreg[8];
#pragma unroll
    for (int q = 0; q < 8; q++) hreg[q] = make_float4(0.f, 0.f, 0.f, 0.f);

    const float4* w1v = (const float4*)sW1;
    const float4* scv = (const float4*)sc;
    const float4* shv = (const float4*)sh;

    for (int t = 0; t < T_STEPS; t++) {
        const unsigned tag = (unsigned)(t + 1);

        // Prefetch x_proj entries (lane 0)
        float xpo = 0.f, xpf = 0.f, xpi = 0.f, xpg = 0.f;
        if (lane == 0) {
            const float* xpt = g_xp + (size_t)t * GATES;
            xpf = xpt[HID + j];
            xpi = xpt[2 * HID + j];
            xpg = xpt[3 * HID + j];
            xpo = xpt[j];
        }

        // ---- Phase 1a (critical): f, i, g dots -> publish c ----
        float af = 0.f, ai = 0.f, ag = 0.f;
        const float4* wpg = w1v + (size_t)(0 * 8 + w) * 256;
#pragma unroll
        for (int q = 0; q < 8; q++) {
            float4 hv = hreg[q];
            float4 vf = wf[q], vi = wi[q];
            af += vf.x * hv.x + vf.y * hv.y + vf.z * hv.z + vf.w * hv.w;
            ai += vi.x * hv.x + vi.y * hv.y + vi.z * hv.z + vi.w * hv.w;
            float4 vg = wpg[lane + 32 * q];
            ag += vg.x * hv.x + vg.y * hv.y + vg.z * hv.z + vg.w * hv.w;
        }
#pragma unroll
        for (int off = 16; off; off >>= 1) {
            af += __shfl_xor_sync(0xffffffffu, af, off);
            ai += __shfl_xor_sync(0xffffffffu, ai, off);
            ag += __shfl_xor_sync(0xffffffffu, ag, off);
        }
        if (lane == 0) {
            float f_t = fsigmoid(af + xpf + bg1);
            float i_t = fsigmoid(ai + xpi + bg2);
            c_state = f_t * c_state + i_t * ftanh(ag + xpg + bg3);
            publish(g_cpack, j, tag, c_state);   // barrier-1 + data, fused
        }

        // ---- Phase 1b (off critical path): o and W_hr dots ----
        float ao = 0.f, ar = 0.f;
        const float4* wpr = w1v + (size_t)(1 * 8 + w) * 256;
#pragma unroll
        for (int q = 0; q < 8; q++) {
            float4 hv = hreg[q];
            float4 vo = wo[q];
            ao += vo.x * hv.x + vo.y * hv.y + vo.z * hv.z + vo.w * hv.w;
            float4 vr = wpr[lane + 32 * q];
            ar += vr.x * hv.x + vr.y * hv.y + vr.z * hv.z + vr.w * hv.w;
        }
#pragma unroll
        for (int off = 16; off; off >>= 1) {
            ao += __shfl_xor_sync(0xffffffffu, ao, off);
            ar += __shfl_xor_sync(0xffffffffu, ar, off);
        }
        float o_val = 0.f, r1 = 0.f;
        if (lane == 0) {
            o_val = fsigmoid(ao + xpo + bg0);
            r1 = ar;
        }

        // ---- Gather c_t (grid barrier + data) ----
        poll_gather4(g_cpack, tag, sc, tid);
        __syncthreads();

        // ---- Phase 2: r2 = c_t . W_cr[:,j] ----
        float a2 = 0.f;
#pragma unroll
        for (int q = 0; q < 8; q++) {
            float4 cv = scv[lane + 32 * q];
            float4 wv = wcr[q];
            a2 += wv.x * cv.x + wv.y * cv.y + wv.z * cv.z + wv.w * cv.w;
        }
#pragma unroll
        for (int off = 16; off; off >>= 1)
            a2 += __shfl_xor_sync(0xffffffffu, a2, off);

        if (lane == 0) {
            float hn = o_val * ftanh(r1 + a2 + brj);
            publish(g_hpack, j, tag, hn);        // publish FIRST (critical)
            out[(size_t)t * HID + j] = hn;       // then archive
        }

        // ---- Gather h_t ----
        poll_gather4(g_hpack, tag, sh, tid);
        __syncthreads();
#pragma unroll
        for (int q = 0; q < 8; q++)
            hreg[q] = shv[lane + 32 * q];
    }
}

// ----------------------------------------------------------------------------
// Launch
// ----------------------------------------------------------------------------
extern "C" void kernel_launch(void* const* d_in, const int* in_sizes, int n_in,
                              void* d_out, int out_size) {
    const float* x    = (const float*)d_in[0];   // [4096, 512]
    const float* W_xg = (const float*)d_in[1];   // [512, 4096]
    const float* W_hg = (const float*)d_in[2];   // [1024, 4096]
    const float* b_g  = (const float*)d_in[3];   // [1, 4096]
    const float* W_cr = (const float*)d_in[4];   // [1024, 1024]
    const float* W_hr = (const float*)d_in[5];   // [1024, 1024]
    const float* b_r  = (const float*)d_in[6];   // [1, 1024]
    float* out = (float*)d_out;                  // [4096, 1, 1024]

    (void)in_sizes; (void)n_in; (void)out_size;

    dim3 ggrid(GATES / 128, T_STEPS / 128);
    sgemm_xproj<<<ggrid, 256>>>(x, W_xg);

    cudaFuncSetAttribute(lstm_recur, cudaFuncAttributeMaxDynamicSharedMemorySize,
                         SMEM_BYTES);
    lstm_recur<<<NCTA, NTHREADS, SMEM_BYTES>>>(W_hg, W_hr, W_cr, b_g, b_r, out);
}